// round 16
// baseline (speedup 1.0000x reference)
#include <cuda_runtime.h>
#include <cuda_bf16.h>
#include <cstdint>

#define TT    2048
#define DM    2560
#define NH    8
#define NKV   4
#define HDIM  256
#define SEQL  8192
#define PREVL 4096
#define ATT_SCALE 0.0625f

// Scratch (device globals; no runtime allocation allowed)
__device__ float g_q[TT * NH * HDIM];        // post rmsnorm+rope, *SCALE, tf32-rounded
__device__ float g_k[TT * NKV * HDIM];       // post rmsnorm+rope, tf32-rounded
__device__ float g_v[TT * NKV * HDIM];       // tf32-rounded (V-GEMM epilogue)
__device__ float g_ctx[TT * NH * HDIM];      // tf32-rounded (attention epilogue)
__device__ float g_kc[PREVL * NKV * HDIM];   // tf32-rounded k_cache[0:PREVL]
__device__ float g_vc[PREVL * NKV * HDIM];   // tf32-rounded v_cache[0:PREVL]
__device__ float g_x [TT * DM];              // tf32-rounded x
__device__ float g_wq[NH  * HDIM * DM];      // tf32-rounded weights
__device__ float g_wk[NKV * HDIM * DM];
__device__ float g_wv[NKV * HDIM * DM];
__device__ float g_wo[DM * NH * HDIM];

__device__ __forceinline__ uint32_t f2tf(float x) {
    uint32_t r;
    asm("cvt.rna.tf32.f32 %0, %1;" : "=r"(r) : "f"(x));
    return r;
}

__device__ __forceinline__ void mma8(float& c0, float& c1, float& c2, float& c3,
                                     uint32_t a0, uint32_t a1, uint32_t a2, uint32_t a3,
                                     uint32_t b0, uint32_t b1) {
    asm volatile(
        "mma.sync.aligned.m16n8k8.row.col.f32.tf32.tf32.f32 "
        "{%0,%1,%2,%3},{%4,%5,%6,%7},{%8,%9},{%0,%1,%2,%3};\n"
        : "+f"(c0), "+f"(c1), "+f"(c2), "+f"(c3)
        : "r"(a0), "r"(a1), "r"(a2), "r"(a3), "r"(b0), "r"(b1));
}

__device__ __forceinline__ void cpa16(uint32_t dst, const float* src) {
    asm volatile("cp.async.cg.shared.global [%0], [%1], 16;" :: "r"(dst), "l"(src));
}

// ---------------------------------------------------------------------------
// roundcpy: dst = tf32_round(src), float4 granularity (idempotent).
// ---------------------------------------------------------------------------
__global__ void __launch_bounds__(256) roundcpy(float4* __restrict__ dst,
                                                const float4* __restrict__ src, int n4) {
    for (int i = blockIdx.x * blockDim.x + threadIdx.x; i < n4;
         i += gridDim.x * blockDim.x) {
        float4 v = src[i];
        v.x = __uint_as_float(f2tf(v.x));
        v.y = __uint_as_float(f2tf(v.y));
        v.z = __uint_as_float(f2tf(v.z));
        v.w = __uint_as_float(f2tf(v.w));
        dst[i] = v;
    }
}

// ---------------------------------------------------------------------------
// tf32 GEMM on pre-rounded inputs:  C[M,N] = A[M,K] * B[N,K]^T
// 128x128 tile, ktile=16, cp.async 3-stage, 8 warps (4x2), warp tile 32x64.
// ROUND: tf32-round output (for V).
// ---------------------------------------------------------------------------
#define GST 20   // smem k-stride (16 + 4 pad)
#define GSTAGE (2 * 128 * GST)   // floats per stage (A tile + B tile)
template <bool ROUND>
__global__ void __launch_bounds__(256, 2) gemm_pre(const float* __restrict__ A,
                                                   const float* __restrict__ B,
                                                   float* __restrict__ C,
                                                   int M, int N, int K) {
    extern __shared__ __align__(16) uint32_t gsm[];
    const int tid = threadIdx.x;
    const int lane = tid & 31;
    const int warp = tid >> 5;
    const int wy = warp >> 1;
    const int wx = warp & 1;
    const int bm = blockIdx.y * 128;
    const int bn = blockIdx.x * 128;
    const uint32_t sbase = (uint32_t)__cvta_generic_to_shared(gsm);

    auto issue = [&](int kt, int s) {
        const uint32_t abase = sbase + (uint32_t)(s * GSTAGE) * 4u;
        const uint32_t bbase = abase + (uint32_t)(128 * GST) * 4u;
        const float* ap = A + (size_t)bm * K + kt * 16;
        const float* bp = B + (size_t)bn * K + kt * 16;
#pragma unroll
        for (int i = 0; i < 2; i++) {
            int c = tid * 2 + i;        // 0..511
            int r = c >> 2;             // 0..127
            int c4 = (c & 3) * 4;       // 0,4,8,12
            cpa16(abase + (uint32_t)(r * GST + c4) * 4u, ap + (size_t)r * K + c4);
            cpa16(bbase + (uint32_t)(r * GST + c4) * 4u, bp + (size_t)r * K + c4);
        }
        asm volatile("cp.async.commit_group;");
    };

    const int nk = K >> 4;
    issue(0, 0);
    issue(1, 1);

    float acc[2][8][4];
#pragma unroll
    for (int i = 0; i < 2; i++)
#pragma unroll
        for (int j = 0; j < 8; j++)
#pragma unroll
            for (int e = 0; e < 4; e++) acc[i][j][e] = 0.f;

    for (int kt = 0; kt < nk; kt++) {
        if (kt + 1 < nk) asm volatile("cp.async.wait_group 1;");
        else             asm volatile("cp.async.wait_group 0;");
        __syncthreads();
        if (kt + 2 < nk) issue(kt + 2, (kt + 2) % 3);

        const uint32_t* as = gsm + (kt % 3) * GSTAGE;
        const uint32_t* bs = as + 128 * GST;
#pragma unroll
        for (int c = 0; c < 2; c++) {
            const int kk = 8 * c;
            uint32_t af[2][4];
#pragma unroll
            for (int mt = 0; mt < 2; mt++) {
                int m = wy * 32 + mt * 16 + (lane >> 2);
                af[mt][0] = as[m * GST + kk + (lane & 3)];
                af[mt][1] = as[(m + 8) * GST + kk + (lane & 3)];
                af[mt][2] = as[m * GST + kk + (lane & 3) + 4];
                af[mt][3] = as[(m + 8) * GST + kk + (lane & 3) + 4];
            }
            uint32_t bf[8][2];
#pragma unroll
            for (int nt = 0; nt < 8; nt++) {
                int n = wx * 64 + nt * 8 + (lane >> 2);
                bf[nt][0] = bs[n * GST + kk + (lane & 3)];
                bf[nt][1] = bs[n * GST + kk + (lane & 3) + 4];
            }
#pragma unroll
            for (int mt = 0; mt < 2; mt++)
#pragma unroll
                for (int nt = 0; nt < 8; nt++)
                    mma8(acc[mt][nt][0], acc[mt][nt][1], acc[mt][nt][2], acc[mt][nt][3],
                         af[mt][0], af[mt][1], af[mt][2], af[mt][3],
                         bf[nt][0], bf[nt][1]);
        }
    }

#pragma unroll
    for (int mt = 0; mt < 2; mt++) {
        int row = bm + wy * 32 + mt * 16 + (lane >> 2);
#pragma unroll
        for (int nt = 0; nt < 8; nt++) {
            int col = bn + wx * 64 + nt * 8 + 2 * (lane & 3);
            float2 o0 = make_float2(acc[mt][nt][0], acc[mt][nt][1]);
            float2 o1 = make_float2(acc[mt][nt][2], acc[mt][nt][3]);
            if (ROUND) {
                o0.x = __uint_as_float(f2tf(o0.x)); o0.y = __uint_as_float(f2tf(o0.y));
                o1.x = __uint_as_float(f2tf(o1.x)); o1.y = __uint_as_float(f2tf(o1.y));
            }
            *(float2*)&C[(size_t)row * N + col] = o0;
            *(float2*)&C[(size_t)(row + 8) * N + col] = o1;
        }
    }
}

// ---------------------------------------------------------------------------
// RMSNorm + RoPE (+SCALE for q), in place; outputs tf32-rounded.
// ---------------------------------------------------------------------------
__global__ void __launch_bounds__(HDIM) rms_rope_kernel(const float* __restrict__ q_scale,
                                                        const float* __restrict__ k_scale,
                                                        const float* __restrict__ cosb,
                                                        const float* __restrict__ sinb) {
    const int t = blockIdx.x;
    const int hy = blockIdx.y;
    const int d = threadIdx.x;

    float* buf;
    const float* sc;
    bool isq;
    if (hy < NH) { buf = &g_q[((size_t)t * NH + hy) * HDIM]; sc = q_scale; isq = true; }
    else         { buf = &g_k[((size_t)t * NKV + (hy - NH)) * HDIM]; sc = k_scale; isq = false; }

    float xv = buf[d];
    int dp = (d < 128) ? d + 128 : d - 128;
    float xp = buf[dp];

    __shared__ float red[8];
    float s = xv * xv;
#pragma unroll
    for (int m = 16; m; m >>= 1) s += __shfl_xor_sync(0xffffffffu, s, m);
    if ((d & 31) == 0) red[d >> 5] = s;
    __syncthreads();
    if (d == 0) {
        float v = 0.f;
#pragma unroll
        for (int i = 0; i < 8; i++) v += red[i];
        red[0] = v;
    }
    __syncthreads();
    float inv = rsqrtf(red[0] * (1.0f / HDIM) + 1e-6f);

    float xn  = xv * inv * (1.f + sc[d]);
    float xpn = xp * inv * (1.f + sc[dp]);
    float rot = (d < 128) ? -xpn : xpn;
    float out = xn * cosb[t * HDIM + d] + rot * sinb[t * HDIM + d];
    if (isq) out *= ATT_SCALE;
    buf[d] = __uint_as_float(f2tf(out));
}

// ---------------------------------------------------------------------------
// Flash attention, tf32, cp.async 3-stage over 32-key blocks, 3 syncs/block.
// grid (32, 8), 256 threads = 8 warps: 4 row-groups x 2 dim-halves.
// ---------------------------------------------------------------------------
#define KROW 260                      // K/V smem row stride
#define KVST (32 * KROW)              // floats per K (or V) tile
#define SPW  36                       // score/P row stride (32 + 4)
__global__ void __launch_bounds__(256, 1) attn_kernel() {
    extern __shared__ __align__(16) float sm[];
    // stage s: K at sm + s*2*KVST, V at +KVST
    float* S0 = sm + 3 * 2 * KVST;    // [64][SPW]
    float* S1 = S0 + 64 * SPW;
    float* Pm = S1 + 64 * SPW;
    uint32_t* Pu = (uint32_t*)Pm;
    const uint32_t smem_u = (uint32_t)__cvta_generic_to_shared(sm);

    const int tid  = threadIdx.x;
    const int lane = tid & 31;
    const int warp = tid >> 5;
    const int rg   = warp >> 1;
    const int half = warp & 1;
    const int m0   = rg * 16;
    const int d0   = half * 128;
    const int lq   = lane >> 2;
    const int lk   = lane & 3;

    const int qt = 31 - blockIdx.x;   // heavy tiles first
    const int h  = blockIdx.y;
    const int kvh = h >> 1;
    const int t0 = qt * 64;
    const int nb = 130 + 2 * qt;      // 32-key blocks covering [0, PREVL+t0+64)

    auto issue = [&](int b, int s) {
        const int s0 = b * 32;
        const float* kb;
        const float* vb;
        if (s0 < PREVL) {
            kb = g_kc + ((size_t)s0 * NKV + kvh) * HDIM;
            vb = g_vc + ((size_t)s0 * NKV + kvh) * HDIM;
        } else {
            kb = g_k + ((size_t)(s0 - PREVL) * NKV + kvh) * HDIM;
            vb = g_v + ((size_t)(s0 - PREVL) * NKV + kvh) * HDIM;
        }
        const uint32_t kd = smem_u + (uint32_t)(s * 2 * KVST) * 4u;
        const uint32_t vd = kd + (uint32_t)KVST * 4u;
#pragma unroll
        for (int i = 0; i < 8; i++) {
            int idx = tid + i * 256;   // 0..2047
            int r  = idx >> 6;         // key row 0..31
            int c4 = (idx & 63) * 4;   // dim
            cpa16(kd + (uint32_t)(r * KROW + c4) * 4u, kb + (size_t)r * (NKV * HDIM) + c4);
            cpa16(vd + (uint32_t)(r * KROW + c4) * 4u, vb + (size_t)r * (NKV * HDIM) + c4);
        }
        asm volatile("cp.async.commit_group;");
    };

    // Q fragments (pre-rounded tf32 bits)
    uint32_t qf[16][4];
    {
        const float* qb  = g_q + (((size_t)(t0 + m0 + lq)) * NH + h) * HDIM + d0;
        const float* qb8 = qb + (size_t)8 * NH * HDIM;
#pragma unroll
        for (int c = 0; c < 16; c++) {
            qf[c][0] = __float_as_uint(qb[8 * c + lk]);
            qf[c][1] = __float_as_uint(qb8[8 * c + lk]);
            qf[c][2] = __float_as_uint(qb[8 * c + lk + 4]);
            qf[c][3] = __float_as_uint(qb8[8 * c + lk + 4]);
        }
    }

    float acc[16][4];
#pragma unroll
    for (int nt = 0; nt < 16; nt++)
#pragma unroll
        for (int e = 0; e < 4; e++) acc[nt][e] = 0.f;
    float mrow[2] = {-1e30f, -1e30f};
    float lrow[2] = {0.f, 0.f};

    issue(0, 0);
    issue(1, 1);

    for (int b = 0; b < nb; b++) {
        const int st = b % 3;
        if (b + 1 < nb) asm volatile("cp.async.wait_group 1;");
        else            asm volatile("cp.async.wait_group 0;");
        __syncthreads();   // A: block b ready; prev iteration fully consumed
        if (b + 2 < nb) issue(b + 2, (b + 2) % 3);

        const float* ksb = sm + st * 2 * KVST;
        const float* vsb = ksb + KVST;

        // S_partial = Q_half * K_half^T : 4 n-tiles over 32 keys
        float sf[4][4];
#pragma unroll
        for (int nt = 0; nt < 4; nt++)
#pragma unroll
            for (int e = 0; e < 4; e++) sf[nt][e] = 0.f;
#pragma unroll
        for (int c = 0; c < 16; c++) {
            const int dd = d0 + 8 * c;
#pragma unroll
            for (int nt = 0; nt < 4; nt++) {
                uint32_t b0 = __float_as_uint(ksb[(nt * 8 + lq) * KROW + dd + lk]);
                uint32_t b1 = __float_as_uint(ksb[(nt * 8 + lq) * KROW + dd + lk + 4]);
                mma8(sf[nt][0], sf[nt][1], sf[nt][2], sf[nt][3],
                     qf[c][0], qf[c][1], qf[c][2], qf[c][3], b0, b1);
            }
        }

        // each half writes its own S buffer
        {
            float* Sw = half ? S1 : S0;
#pragma unroll
            for (int nt = 0; nt < 4; nt++) {
                int col = nt * 8 + 2 * lk;
                Sw[(m0 + lq) * SPW + col]     = sf[nt][0];
                Sw[(m0 + lq) * SPW + col + 1] = sf[nt][1];
                Sw[(m0 + lq + 8) * SPW + col]     = sf[nt][2];
                Sw[(m0 + lq + 8) * SPW + col + 1] = sf[nt][3];
            }
        }
        __syncthreads();   // B: S0/S1 complete

        // sum halves in registers
#pragma unroll
        for (int nt = 0; nt < 4; nt++) {
            int col = nt * 8 + 2 * lk;
            sf[nt][0] = S0[(m0 + lq) * SPW + col]      + S1[(m0 + lq) * SPW + col];
            sf[nt][1] = S0[(m0 + lq) * SPW + col + 1]  + S1[(m0 + lq) * SPW + col + 1];
            sf[nt][2] = S0[(m0 + lq + 8) * SPW + col]     + S1[(m0 + lq + 8) * SPW + col];
            sf[nt][3] = S0[(m0 + lq + 8) * SPW + col + 1] + S1[(m0 + lq + 8) * SPW + col + 1];
        }

        // causal mask (last two blocks of this tile only)
        const int rel = b * 32 - PREVL - t0;
        if (rel > -32) {
            const int qr0 = m0 + lq;
            const int qr1 = m0 + lq + 8;
#pragma unroll
            for (int nt = 0; nt < 4; nt++) {
                int col = nt * 8 + 2 * lk;
                if (rel + col > qr0)     sf[nt][0] = -1e30f;
                if (rel + col + 1 > qr0) sf[nt][1] = -1e30f;
                if (rel + col > qr1)     sf[nt][2] = -1e30f;
                if (rel + col + 1 > qr1) sf[nt][3] = -1e30f;
            }
        }

        // online softmax (rows m0+lq, m0+lq+8)
#pragma unroll
        for (int j = 0; j < 2; j++) {
            float rmax = -1e30f;
#pragma unroll
            for (int nt = 0; nt < 4; nt++) {
                rmax = fmaxf(rmax, sf[nt][2 * j]);
                rmax = fmaxf(rmax, sf[nt][2 * j + 1]);
            }
            rmax = fmaxf(rmax, __shfl_xor_sync(0xffffffffu, rmax, 1));
            rmax = fmaxf(rmax, __shfl_xor_sync(0xffffffffu, rmax, 2));
            float mnew = fmaxf(mrow[j], rmax);
            float resc = __expf(mrow[j] - mnew);
            mrow[j] = mnew;
            float rs = 0.f;
#pragma unroll
            for (int nt = 0; nt < 4; nt++) {
                float p0 = __expf(sf[nt][2 * j] - mnew);
                float p1 = __expf(sf[nt][2 * j + 1] - mnew);
                sf[nt][2 * j] = p0;
                sf[nt][2 * j + 1] = p1;
                rs += p0 + p1;
            }
            rs += __shfl_xor_sync(0xffffffffu, rs, 1);
            rs += __shfl_xor_sync(0xffffffffu, rs, 2);
            lrow[j] = lrow[j] * resc + rs;
#pragma unroll
            for (int nt = 0; nt < 16; nt++) {
                acc[nt][2 * j] *= resc;
                acc[nt][2 * j + 1] *= resc;
            }
        }

        // write P (tf32 bits) — half 0 only
        if (half == 0) {
#pragma unroll
            for (int nt = 0; nt < 4; nt++) {
                int col = nt * 8 + 2 * lk;
                Pu[(m0 + lq) * SPW + col]     = f2tf(sf[nt][0]);
                Pu[(m0 + lq) * SPW + col + 1] = f2tf(sf[nt][1]);
                Pu[(m0 + lq + 8) * SPW + col]     = f2tf(sf[nt][2]);
                Pu[(m0 + lq + 8) * SPW + col + 1] = f2tf(sf[nt][3]);
            }
        }
        __syncthreads();   // E: P ready

        // ctx_half += P * V_half
#pragma unroll
        for (int kc2 = 0; kc2 < 4; kc2++) {
            uint32_t a0 = Pu[(m0 + lq) * SPW + kc2 * 8 + lk];
            uint32_t a1 = Pu[(m0 + lq + 8) * SPW + kc2 * 8 + lk];
            uint32_t a2 = Pu[(m0 + lq) * SPW + kc2 * 8 + lk + 4];
            uint32_t a3 = Pu[(m0 + lq + 8) * SPW + kc2 * 8 + lk + 4];
#pragma unroll
            for (int nt = 0; nt < 16; nt++) {
                int d = d0 + nt * 8 + lq;
                uint32_t b0 = __float_as_uint(vsb[(kc2 * 8 + lk) * KROW + d]);
                uint32_t b1 = __float_as_uint(vsb[(kc2 * 8 + lk + 4) * KROW + d]);
                mma8(acc[nt][0], acc[nt][1], acc[nt][2], acc[nt][3],
                     a0, a1, a2, a3, b0, b1);
            }
        }
        // no trailing sync needed: sync A of next iteration guards all reuse
    }

    // epilogue (tf32-rounded ctx, ready for raw-loading out-GEMM)
    float linv0 = 1.f / lrow[0];
    float linv1 = 1.f / lrow[1];
    {
        size_t row0 = (size_t)(t0 + m0 + lq) * (NH * HDIM) + (size_t)h * HDIM;
        size_t row1 = row0 + (size_t)8 * NH * HDIM;
#pragma unroll
        for (int nt = 0; nt < 16; nt++) {
            int col = d0 + nt * 8 + 2 * lk;
            float2 o0 = make_float2(__uint_as_float(f2tf(acc[nt][0] * linv0)),
                                    __uint_as_float(f2tf(acc[nt][1] * linv0)));
            float2 o1 = make_float2(__uint_as_float(f2tf(acc[nt][2] * linv1)),
                                    __uint_as_float(f2tf(acc[nt][3] * linv1)));
            *(float2*)&g_ctx[row0 + col] = o0;
            *(float2*)&g_ctx[row1 + col] = o1;
        }
    }
}

// ---------------------------------------------------------------------------
extern "C" void kernel_launch(void* const* d_in, const int* in_sizes, int n_in,
                              void* d_out, int out_size) {
    const float* x   = (const float*)d_in[0];
    const float* Wq  = (const float*)d_in[1];
    const float* Wk  = (const float*)d_in[2];
    const float* Wv  = (const float*)d_in[3];
    const float* Wo  = (const float*)d_in[4];
    const float* qsc = (const float*)d_in[5];
    const float* ksc = (const float*)d_in[6];
    const float* kc  = (const float*)d_in[7];
    const float* vc  = (const float*)d_in[8];
    const float* cs  = (const float*)d_in[9];
    const float* sn  = (const float*)d_in[10];
    float* out = (float*)d_out;

    float *q, *k, *v, *ctx, *px, *pwq, *pwk, *pwv, *pwo, *pkc, *pvc;
    cudaGetSymbolAddress((void**)&q,   g_q);
    cudaGetSymbolAddress((void**)&k,   g_k);
    cudaGetSymbolAddress((void**)&v,   g_v);
    cudaGetSymbolAddress((void**)&ctx, g_ctx);
    cudaGetSymbolAddress((void**)&px,  g_x);
    cudaGetSymbolAddress((void**)&pwq, g_wq);
    cudaGetSymbolAddress((void**)&pwk, g_wk);
    cudaGetSymbolAddress((void**)&pwv, g_wv);
    cudaGetSymbolAddress((void**)&pwo, g_wo);
    cudaGetSymbolAddress((void**)&pkc, g_kc);
    cudaGetSymbolAddress((void**)&pvc, g_vc);

    // Pre-round all GEMM/attention operands to tf32 (idempotent; bit-preserving)
    roundcpy<<<2048, 256>>>((float4*)px,  (const float4*)x,  TT * DM / 4);
    roundcpy<<<2048, 256>>>((float4*)pwq, (const float4*)Wq, NH * HDIM * DM / 4);
    roundcpy<<<1024, 256>>>((float4*)pwk, (const float4*)Wk, NKV * HDIM * DM / 4);
    roundcpy<<<1024, 256>>>((float4*)pwv, (const float4*)Wv, NKV * HDIM * DM / 4);
    roundcpy<<<2048, 256>>>((float4*)pwo, (const float4*)Wo, DM * NH * HDIM / 4);
    roundcpy<<<2048, 256>>>((float4*)pkc, (const float4*)kc, PREVL * NKV * HDIM / 4);
    roundcpy<<<2048, 256>>>((float4*)pvc, (const float4*)vc, PREVL * NKV * HDIM / 4);

    // QKV projections (cp.async 3-stage tf32 GEMM)
    const int gsmem = 3 * GSTAGE * 4;
    cudaFuncSetAttribute(gemm_pre<false>, cudaFuncAttributeMaxDynamicSharedMemorySize, gsmem);
    cudaFuncSetAttribute(gemm_pre<true>,  cudaFuncAttributeMaxDynamicSharedMemorySize, gsmem);
    gemm_pre<false><<<dim3(16, 16), 256, gsmem>>>(px, pwq, q, TT, NH * HDIM, DM);
    gemm_pre<false><<<dim3(8, 16), 256, gsmem>>>(px, pwk, k, TT, NKV * HDIM, DM);
    gemm_pre<true ><<<dim3(8, 16), 256, gsmem>>>(px, pwv, v, TT, NKV * HDIM, DM);

    // RMSNorm + RoPE (+SCALE on q), outputs tf32-rounded
    rms_rope_kernel<<<dim3(TT, NH + NKV), HDIM>>>(qsc, ksc, cs, sn);

    // Attention (tf32, cp.async 3-stage, 3 syncs/block)
    const int asmem = (3 * 2 * KVST + 3 * 64 * SPW) * 4;
    cudaFuncSetAttribute(attn_kernel, cudaFuncAttributeMaxDynamicSharedMemorySize, asmem);
    attn_kernel<<<dim3(32, NH), 256, asmem>>>();

    // Output projection (raw fp32 result)
    gemm_pre<false><<<dim3(20, 16), 256, gsmem>>>(ctx, pwo, out, TT, DM, NH * HDIM);
}

// round 17
// speedup vs baseline: 1.0006x; 1.0006x over previous
#include <cuda_runtime.h>
#include <cuda_bf16.h>
#include <cstdint>

#define TT    2048
#define DM    2560
#define NH    8
#define NKV   4
#define HDIM  256
#define SEQL  8192
#define PREVL 4096
#define ATT_SCALE 0.0625f

// Scratch (device globals; no runtime allocation allowed)
__device__ float g_q[TT * NH * HDIM];        // post rmsnorm+rope, *SCALE, tf32-rounded
__device__ float g_k[TT * NKV * HDIM];       // post rmsnorm+rope, tf32-rounded
__device__ float g_v[TT * NKV * HDIM];       // tf32-rounded (V-GEMM epilogue)
__device__ float g_ctx[TT * NH * HDIM];      // tf32-rounded (attention epilogue)
__device__ float g_kc[PREVL * NKV * HDIM];   // tf32-rounded k_cache[0:PREVL]
__device__ float g_vc[PREVL * NKV * HDIM];   // tf32-rounded v_cache[0:PREVL]
__device__ float g_x [TT * DM];              // tf32-rounded x
__device__ float g_wq[NH  * HDIM * DM];      // tf32-rounded weights
__device__ float g_wk[NKV * HDIM * DM];
__device__ float g_wv[NKV * HDIM * DM];
__device__ float g_wo[DM * NH * HDIM];

__device__ __forceinline__ uint32_t f2tf(float x) {
    uint32_t r;
    asm("cvt.rna.tf32.f32 %0, %1;" : "=r"(r) : "f"(x));
    return r;
}

__device__ __forceinline__ void mma8(float& c0, float& c1, float& c2, float& c3,
                                     uint32_t a0, uint32_t a1, uint32_t a2, uint32_t a3,
                                     uint32_t b0, uint32_t b1) {
    asm volatile(
        "mma.sync.aligned.m16n8k8.row.col.f32.tf32.tf32.f32 "
        "{%0,%1,%2,%3},{%4,%5,%6,%7},{%8,%9},{%0,%1,%2,%3};\n"
        : "+f"(c0), "+f"(c1), "+f"(c2), "+f"(c3)
        : "r"(a0), "r"(a1), "r"(a2), "r"(a3), "r"(b0), "r"(b1));
}

__device__ __forceinline__ void cpa16(uint32_t dst, const float* src) {
    asm volatile("cp.async.cg.shared.global [%0], [%1], 16;" :: "r"(dst), "l"(src));
}

// ---------------------------------------------------------------------------
// roundcpy: dst = tf32_round(src), float4 granularity (idempotent).
// ---------------------------------------------------------------------------
__global__ void __launch_bounds__(256) roundcpy(float4* __restrict__ dst,
                                                const float4* __restrict__ src, int n4) {
    for (int i = blockIdx.x * blockDim.x + threadIdx.x; i < n4;
         i += gridDim.x * blockDim.x) {
        float4 v = src[i];
        v.x = __uint_as_float(f2tf(v.x));
        v.y = __uint_as_float(f2tf(v.y));
        v.z = __uint_as_float(f2tf(v.z));
        v.w = __uint_as_float(f2tf(v.w));
        dst[i] = v;
    }
}

// ---------------------------------------------------------------------------
// tf32 GEMM on pre-rounded inputs:  C[M,N] = A[M,K] * B[N,K]^T
// 128x128 tile, ktile=16, cp.async 3-stage, 8 warps (4x2), warp tile 32x64.
// ROUND: tf32-round output (for V).
// ---------------------------------------------------------------------------
#define GST 20   // smem k-stride (16 + 4 pad)
#define GSTAGE (2 * 128 * GST)   // floats per stage (A tile + B tile)
template <bool ROUND>
__global__ void __launch_bounds__(256, 2) gemm_pre(const float* __restrict__ A,
                                                   const float* __restrict__ B,
                                                   float* __restrict__ C,
                                                   int M, int N, int K) {
    extern __shared__ __align__(16) uint32_t gsm[];
    const int tid = threadIdx.x;
    const int lane = tid & 31;
    const int warp = tid >> 5;
    const int wy = warp >> 1;
    const int wx = warp & 1;
    const int bm = blockIdx.y * 128;
    const int bn = blockIdx.x * 128;
    const uint32_t sbase = (uint32_t)__cvta_generic_to_shared(gsm);

    auto issue = [&](int kt, int s) {
        const uint32_t abase = sbase + (uint32_t)(s * GSTAGE) * 4u;
        const uint32_t bbase = abase + (uint32_t)(128 * GST) * 4u;
        const float* ap = A + (size_t)bm * K + kt * 16;
        const float* bp = B + (size_t)bn * K + kt * 16;
#pragma unroll
        for (int i = 0; i < 2; i++) {
            int c = tid * 2 + i;        // 0..511
            int r = c >> 2;             // 0..127
            int c4 = (c & 3) * 4;       // 0,4,8,12
            cpa16(abase + (uint32_t)(r * GST + c4) * 4u, ap + (size_t)r * K + c4);
            cpa16(bbase + (uint32_t)(r * GST + c4) * 4u, bp + (size_t)r * K + c4);
        }
        asm volatile("cp.async.commit_group;");
    };

    const int nk = K >> 4;
    issue(0, 0);
    issue(1, 1);

    float acc[2][8][4];
#pragma unroll
    for (int i = 0; i < 2; i++)
#pragma unroll
        for (int j = 0; j < 8; j++)
#pragma unroll
            for (int e = 0; e < 4; e++) acc[i][j][e] = 0.f;

    for (int kt = 0; kt < nk; kt++) {
        if (kt + 1 < nk) asm volatile("cp.async.wait_group 1;");
        else             asm volatile("cp.async.wait_group 0;");
        __syncthreads();
        if (kt + 2 < nk) issue(kt + 2, (kt + 2) % 3);

        const uint32_t* as = gsm + (kt % 3) * GSTAGE;
        const uint32_t* bs = as + 128 * GST;
#pragma unroll
        for (int c = 0; c < 2; c++) {
            const int kk = 8 * c;
            uint32_t af[2][4];
#pragma unroll
            for (int mt = 0; mt < 2; mt++) {
                int m = wy * 32 + mt * 16 + (lane >> 2);
                af[mt][0] = as[m * GST + kk + (lane & 3)];
                af[mt][1] = as[(m + 8) * GST + kk + (lane & 3)];
                af[mt][2] = as[m * GST + kk + (lane & 3) + 4];
                af[mt][3] = as[(m + 8) * GST + kk + (lane & 3) + 4];
            }
            uint32_t bf[8][2];
#pragma unroll
            for (int nt = 0; nt < 8; nt++) {
                int n = wx * 64 + nt * 8 + (lane >> 2);
                bf[nt][0] = bs[n * GST + kk + (lane & 3)];
                bf[nt][1] = bs[n * GST + kk + (lane & 3) + 4];
            }
#pragma unroll
            for (int mt = 0; mt < 2; mt++)
#pragma unroll
                for (int nt = 0; nt < 8; nt++)
                    mma8(acc[mt][nt][0], acc[mt][nt][1], acc[mt][nt][2], acc[mt][nt][3],
                         af[mt][0], af[mt][1], af[mt][2], af[mt][3],
                         bf[nt][0], bf[nt][1]);
        }
    }

#pragma unroll
    for (int mt = 0; mt < 2; mt++) {
        int row = bm + wy * 32 + mt * 16 + (lane >> 2);
#pragma unroll
        for (int nt = 0; nt < 8; nt++) {
            int col = bn + wx * 64 + nt * 8 + 2 * (lane & 3);
            float2 o0 = make_float2(acc[mt][nt][0], acc[mt][nt][1]);
            float2 o1 = make_float2(acc[mt][nt][2], acc[mt][nt][3]);
            if (ROUND) {
                o0.x = __uint_as_float(f2tf(o0.x)); o0.y = __uint_as_float(f2tf(o0.y));
                o1.x = __uint_as_float(f2tf(o1.x)); o1.y = __uint_as_float(f2tf(o1.y));
            }
            *(float2*)&C[(size_t)row * N + col] = o0;
            *(float2*)&C[(size_t)(row + 8) * N + col] = o1;
        }
    }
}

// ---------------------------------------------------------------------------
// RMSNorm + RoPE (+SCALE for q), in place; outputs tf32-rounded.
// ---------------------------------------------------------------------------
__global__ void __launch_bounds__(HDIM) rms_rope_kernel(const float* __restrict__ q_scale,
                                                        const float* __restrict__ k_scale,
                                                        const float* __restrict__ cosb,
                                                        const float* __restrict__ sinb) {
    const int t = blockIdx.x;
    const int hy = blockIdx.y;
    const int d = threadIdx.x;

    float* buf;
    const float* sc;
    bool isq;
    if (hy < NH) { buf = &g_q[((size_t)t * NH + hy) * HDIM]; sc = q_scale; isq = true; }
    else         { buf = &g_k[((size_t)t * NKV + (hy - NH)) * HDIM]; sc = k_scale; isq = false; }

    float xv = buf[d];
    int dp = (d < 128) ? d + 128 : d - 128;
    float xp = buf[dp];

    __shared__ float red[8];
    float s = xv * xv;
#pragma unroll
    for (int m = 16; m; m >>= 1) s += __shfl_xor_sync(0xffffffffu, s, m);
    if ((d & 31) == 0) red[d >> 5] = s;
    __syncthreads();
    if (d == 0) {
        float v = 0.f;
#pragma unroll
        for (int i = 0; i < 8; i++) v += red[i];
        red[0] = v;
    }
    __syncthreads();
    float inv = rsqrtf(red[0] * (1.0f / HDIM) + 1e-6f);

    float xn  = xv * inv * (1.f + sc[d]);
    float xpn = xp * inv * (1.f + sc[dp]);
    float rot = (d < 128) ? -xpn : xpn;
    float out = xn * cosb[t * HDIM + d] + rot * sinb[t * HDIM + d];
    if (isq) out *= ATT_SCALE;
    buf[d] = __uint_as_float(f2tf(out));
}

// ---------------------------------------------------------------------------
// Flash attention, tf32, cp.async 3-stage over 32-key blocks, 3 syncs/block.
// grid (32, 8), 256 threads = 8 warps: 4 row-groups x 2 dim-halves.
// ---------------------------------------------------------------------------
#define KROW 260                      // K/V smem row stride
#define KVST (32 * KROW)              // floats per K (or V) tile
#define SPW  36                       // score/P row stride (32 + 4)
__global__ void __launch_bounds__(256, 1) attn_kernel() {
    extern __shared__ __align__(16) float sm[];
    // stage s: K at sm + s*2*KVST, V at +KVST
    float* S0 = sm + 3 * 2 * KVST;    // [64][SPW]
    float* S1 = S0 + 64 * SPW;
    float* Pm = S1 + 64 * SPW;
    uint32_t* Pu = (uint32_t*)Pm;
    const uint32_t smem_u = (uint32_t)__cvta_generic_to_shared(sm);

    const int tid  = threadIdx.x;
    const int lane = tid & 31;
    const int warp = tid >> 5;
    const int rg   = warp >> 1;
    const int half = warp & 1;
    const int m0   = rg * 16;
    const int d0   = half * 128;
    const int lq   = lane >> 2;
    const int lk   = lane & 3;

    const int qt = 31 - blockIdx.x;   // heavy tiles first
    const int h  = blockIdx.y;
    const int kvh = h >> 1;
    const int t0 = qt * 64;
    const int nb = 130 + 2 * qt;      // 32-key blocks covering [0, PREVL+t0+64)

    auto issue = [&](int b, int s) {
        const int s0 = b * 32;
        const float* kb;
        const float* vb;
        if (s0 < PREVL) {
            kb = g_kc + ((size_t)s0 * NKV + kvh) * HDIM;
            vb = g_vc + ((size_t)s0 * NKV + kvh) * HDIM;
        } else {
            kb = g_k + ((size_t)(s0 - PREVL) * NKV + kvh) * HDIM;
            vb = g_v + ((size_t)(s0 - PREVL) * NKV + kvh) * HDIM;
        }
        const uint32_t kd = smem_u + (uint32_t)(s * 2 * KVST) * 4u;
        const uint32_t vd = kd + (uint32_t)KVST * 4u;
#pragma unroll
        for (int i = 0; i < 8; i++) {
            int idx = tid + i * 256;   // 0..2047
            int r  = idx >> 6;         // key row 0..31
            int c4 = (idx & 63) * 4;   // dim
            cpa16(kd + (uint32_t)(r * KROW + c4) * 4u, kb + (size_t)r * (NKV * HDIM) + c4);
            cpa16(vd + (uint32_t)(r * KROW + c4) * 4u, vb + (size_t)r * (NKV * HDIM) + c4);
        }
        asm volatile("cp.async.commit_group;");
    };

    // Q fragments (pre-rounded tf32 bits)
    uint32_t qf[16][4];
    {
        const float* qb  = g_q + (((size_t)(t0 + m0 + lq)) * NH + h) * HDIM + d0;
        const float* qb8 = qb + (size_t)8 * NH * HDIM;
#pragma unroll
        for (int c = 0; c < 16; c++) {
            qf[c][0] = __float_as_uint(qb[8 * c + lk]);
            qf[c][1] = __float_as_uint(qb8[8 * c + lk]);
            qf[c][2] = __float_as_uint(qb[8 * c + lk + 4]);
            qf[c][3] = __float_as_uint(qb8[8 * c + lk + 4]);
        }
    }

    float acc[16][4];
#pragma unroll
    for (int nt = 0; nt < 16; nt++)
#pragma unroll
        for (int e = 0; e < 4; e++) acc[nt][e] = 0.f;
    float mrow[2] = {-1e30f, -1e30f};
    float lrow[2] = {0.f, 0.f};

    issue(0, 0);
    issue(1, 1);

    for (int b = 0; b < nb; b++) {
        const int st = b % 3;
        if (b + 1 < nb) asm volatile("cp.async.wait_group 1;");
        else            asm volatile("cp.async.wait_group 0;");
        __syncthreads();   // A: block b ready; prev iteration fully consumed
        if (b + 2 < nb) issue(b + 2, (b + 2) % 3);

        const float* ksb = sm + st * 2 * KVST;
        const float* vsb = ksb + KVST;

        // S_partial = Q_half * K_half^T : 4 n-tiles over 32 keys
        float sf[4][4];
#pragma unroll
        for (int nt = 0; nt < 4; nt++)
#pragma unroll
            for (int e = 0; e < 4; e++) sf[nt][e] = 0.f;
#pragma unroll
        for (int c = 0; c < 16; c++) {
            const int dd = d0 + 8 * c;
#pragma unroll
            for (int nt = 0; nt < 4; nt++) {
                uint32_t b0 = __float_as_uint(ksb[(nt * 8 + lq) * KROW + dd + lk]);
                uint32_t b1 = __float_as_uint(ksb[(nt * 8 + lq) * KROW + dd + lk + 4]);
                mma8(sf[nt][0], sf[nt][1], sf[nt][2], sf[nt][3],
                     qf[c][0], qf[c][1], qf[c][2], qf[c][3], b0, b1);
            }
        }

        // each half writes its own S buffer
        {
            float* Sw = half ? S1 : S0;
#pragma unroll
            for (int nt = 0; nt < 4; nt++) {
                int col = nt * 8 + 2 * lk;
                Sw[(m0 + lq) * SPW + col]     = sf[nt][0];
                Sw[(m0 + lq) * SPW + col + 1] = sf[nt][1];
                Sw[(m0 + lq + 8) * SPW + col]     = sf[nt][2];
                Sw[(m0 + lq + 8) * SPW + col + 1] = sf[nt][3];
            }
        }
        __syncthreads();   // B: S0/S1 complete

        // sum halves in registers
#pragma unroll
        for (int nt = 0; nt < 4; nt++) {
            int col = nt * 8 + 2 * lk;
            sf[nt][0] = S0[(m0 + lq) * SPW + col]      + S1[(m0 + lq) * SPW + col];
            sf[nt][1] = S0[(m0 + lq) * SPW + col + 1]  + S1[(m0 + lq) * SPW + col + 1];
            sf[nt][2] = S0[(m0 + lq + 8) * SPW + col]     + S1[(m0 + lq + 8) * SPW + col];
            sf[nt][3] = S0[(m0 + lq + 8) * SPW + col + 1] + S1[(m0 + lq + 8) * SPW + col + 1];
        }

        // causal mask (last two blocks of this tile only)
        const int rel = b * 32 - PREVL - t0;
        if (rel > -32) {
            const int qr0 = m0 + lq;
            const int qr1 = m0 + lq + 8;
#pragma unroll
            for (int nt = 0; nt < 4; nt++) {
                int col = nt * 8 + 2 * lk;
                if (rel + col > qr0)     sf[nt][0] = -1e30f;
                if (rel + col + 1 > qr0) sf[nt][1] = -1e30f;
                if (rel + col > qr1)     sf[nt][2] = -1e30f;
                if (rel + col + 1 > qr1) sf[nt][3] = -1e30f;
            }
        }

        // online softmax (rows m0+lq, m0+lq+8)
#pragma unroll
        for (int j = 0; j < 2; j++) {
            float rmax = -1e30f;
#pragma unroll
            for (int nt = 0; nt < 4; nt++) {
                rmax = fmaxf(rmax, sf[nt][2 * j]);
                rmax = fmaxf(rmax, sf[nt][2 * j + 1]);
            }
            rmax = fmaxf(rmax, __shfl_xor_sync(0xffffffffu, rmax, 1));
            rmax = fmaxf(rmax, __shfl_xor_sync(0xffffffffu, rmax, 2));
            float mnew = fmaxf(mrow[j], rmax);
            float resc = __expf(mrow[j] - mnew);
            mrow[j] = mnew;
            float rs = 0.f;
#pragma unroll
            for (int nt = 0; nt < 4; nt++) {
                float p0 = __expf(sf[nt][2 * j] - mnew);
                float p1 = __expf(sf[nt][2 * j + 1] - mnew);
                sf[nt][2 * j] = p0;
                sf[nt][2 * j + 1] = p1;
                rs += p0 + p1;
            }
            rs += __shfl_xor_sync(0xffffffffu, rs, 1);
            rs += __shfl_xor_sync(0xffffffffu, rs, 2);
            lrow[j] = lrow[j] * resc + rs;
#pragma unroll
            for (int nt = 0; nt < 16; nt++) {
                acc[nt][2 * j] *= resc;
                acc[nt][2 * j + 1] *= resc;
            }
        }

        // write P (tf32 bits) — half 0 only
        if (half == 0) {
#pragma unroll
            for (int nt = 0; nt < 4; nt++) {
                int col = nt * 8 + 2 * lk;
                Pu[(m0 + lq) * SPW + col]     = f2tf(sf[nt][0]);
                Pu[(m0 + lq) * SPW + col + 1] = f2tf(sf[nt][1]);
                Pu[(m0 + lq + 8) * SPW + col]     = f2tf(sf[nt][2]);
                Pu[(m0 + lq + 8) * SPW + col + 1] = f2tf(sf[nt][3]);
            }
        }
        __syncthreads();   // E: P ready

        // ctx_half += P * V_half
#pragma unroll
        for (int kc2 = 0; kc2 < 4; kc2++) {
            uint32_t a0 = Pu[(m0 + lq) * SPW + kc2 * 8 + lk];
            uint32_t a1 = Pu[(m0 + lq + 8) * SPW + kc2 * 8 + lk];
            uint32_t a2 = Pu[(m0 + lq) * SPW + kc2 * 8 + lk + 4];
            uint32_t a3 = Pu[(m0 + lq + 8) * SPW + kc2 * 8 + lk + 4];
#pragma unroll
            for (int nt = 0; nt < 16; nt++) {
                int d = d0 + nt * 8 + lq;
                uint32_t b0 = __float_as_uint(vsb[(kc2 * 8 + lk) * KROW + d]);
                uint32_t b1 = __float_as_uint(vsb[(kc2 * 8 + lk + 4) * KROW + d]);
                mma8(acc[nt][0], acc[nt][1], acc[nt][2], acc[nt][3],
                     a0, a1, a2, a3, b0, b1);
            }
        }
        // no trailing sync needed: sync A of next iteration guards all reuse
    }

    // epilogue (tf32-rounded ctx, ready for raw-loading out-GEMM)
    float linv0 = 1.f / lrow[0];
    float linv1 = 1.f / lrow[1];
    {
        size_t row0 = (size_t)(t0 + m0 + lq) * (NH * HDIM) + (size_t)h * HDIM;
        size_t row1 = row0 + (size_t)8 * NH * HDIM;
#pragma unroll
        for (int nt = 0; nt < 16; nt++) {
            int col = d0 + nt * 8 + 2 * lk;
            float2 o0 = make_float2(__uint_as_float(f2tf(acc[nt][0] * linv0)),
                                    __uint_as_float(f2tf(acc[nt][1] * linv0)));
            float2 o1 = make_float2(__uint_as_float(f2tf(acc[nt][2] * linv1)),
                                    __uint_as_float(f2tf(acc[nt][3] * linv1)));
            *(float2*)&g_ctx[row0 + col] = o0;
            *(float2*)&g_ctx[row1 + col] = o1;
        }
    }
}

// ---------------------------------------------------------------------------
extern "C" void kernel_launch(void* const* d_in, const int* in_sizes, int n_in,
                              void* d_out, int out_size) {
    const float* x   = (const float*)d_in[0];
    const float* Wq  = (const float*)d_in[1];
    const float* Wk  = (const float*)d_in[2];
    const float* Wv  = (const float*)d_in[3];
    const float* Wo  = (const float*)d_in[4];
    const float* qsc = (const float*)d_in[5];
    const float* ksc = (const float*)d_in[6];
    const float* kc  = (const float*)d_in[7];
    const float* vc  = (const float*)d_in[8];
    const float* cs  = (const float*)d_in[9];
    const float* sn  = (const float*)d_in[10];
    float* out = (float*)d_out;

    float *q, *k, *v, *ctx, *px, *pwq, *pwk, *pwv, *pwo, *pkc, *pvc;
    cudaGetSymbolAddress((void**)&q,   g_q);
    cudaGetSymbolAddress((void**)&k,   g_k);
    cudaGetSymbolAddress((void**)&v,   g_v);
    cudaGetSymbolAddress((void**)&ctx, g_ctx);
    cudaGetSymbolAddress((void**)&px,  g_x);
    cudaGetSymbolAddress((void**)&pwq, g_wq);
    cudaGetSymbolAddress((void**)&pwk, g_wk);
    cudaGetSymbolAddress((void**)&pwv, g_wv);
    cudaGetSymbolAddress((void**)&pwo, g_wo);
    cudaGetSymbolAddress((void**)&pkc, g_kc);
    cudaGetSymbolAddress((void**)&pvc, g_vc);

    // Pre-round all GEMM/attention operands to tf32 (idempotent; bit-preserving)
    roundcpy<<<2048, 256>>>((float4*)px,  (const float4*)x,  TT * DM / 4);
    roundcpy<<<2048, 256>>>((float4*)pwq, (const float4*)Wq, NH * HDIM * DM / 4);
    roundcpy<<<1024, 256>>>((float4*)pwk, (const float4*)Wk, NKV * HDIM * DM / 4);
    roundcpy<<<1024, 256>>>((float4*)pwv, (const float4*)Wv, NKV * HDIM * DM / 4);
    roundcpy<<<2048, 256>>>((float4*)pwo, (const float4*)Wo, DM * NH * HDIM / 4);
    roundcpy<<<2048, 256>>>((float4*)pkc, (const float4*)kc, PREVL * NKV * HDIM / 4);
    roundcpy<<<2048, 256>>>((float4*)pvc, (const float4*)vc, PREVL * NKV * HDIM / 4);

    // QKV projections (cp.async 3-stage tf32 GEMM)
    const int gsmem = 3 * GSTAGE * 4;
    cudaFuncSetAttribute(gemm_pre<false>, cudaFuncAttributeMaxDynamicSharedMemorySize, gsmem);
    cudaFuncSetAttribute(gemm_pre<true>,  cudaFuncAttributeMaxDynamicSharedMemorySize, gsmem);
    gemm_pre<false><<<dim3(16, 16), 256, gsmem>>>(px, pwq, q, TT, NH * HDIM, DM);
    gemm_pre<false><<<dim3(8, 16), 256, gsmem>>>(px, pwk, k, TT, NKV * HDIM, DM);
    gemm_pre<true ><<<dim3(8, 16), 256, gsmem>>>(px, pwv, v, TT, NKV * HDIM, DM);

    // RMSNorm + RoPE (+SCALE on q), outputs tf32-rounded
    rms_rope_kernel<<<dim3(TT, NH + NKV), HDIM>>>(qsc, ksc, cs, sn);

    // Attention (tf32, cp.async 3-stage, 3 syncs/block)
    const int asmem = (3 * 2 * KVST + 3 * 64 * SPW) * 4;
    cudaFuncSetAttribute(attn_kernel, cudaFuncAttributeMaxDynamicSharedMemorySize, asmem);
    attn_kernel<<<dim3(32, NH), 256, asmem>>>();

    // Output projection (raw fp32 result)
    gemm_pre<false><<<dim3(20, 16), 256, gsmem>>>(ctx, pwo, out, TT, DM, NH * HDIM);
}